// round 16
// baseline (speedup 1.0000x reference)
#include <cuda_runtime.h>

#define NN 20000
#define EE 40000
#define BB 32
#define SS 32
#define TT 64

#define INV_STEP 15.5f          // (S-1)/(2*R)
#define C_STEP   18.61541988f   // 200*log2(e)/15.5

#define ESEG  2048
#define NCH_N 8
#define NCH_E 16
#define NODE_VB (BB * NCH_N)          // 256
#define EDGE_VB (BB * NCH_E)          // 512
#define HIST_VB (NODE_VB + EDGE_VB)   // 768

#define ROWW  35                      // bins p=-1..33 (guard zones, clamp-free)
#define HISTF (256 * ROWW)            // 8960 floats (divisible by 4)

// prep block ranges
#define ZB 64                          // zero out: 64*256 float4
#define XB ((NN + 255) / 256)          // 79  : pad x -> float4
#define EB ((EE + 255) / 256)          // 157 : edge scatter
#define NB ((NN + 255) / 256)          // 79  : boundaries
#define PREP_BLOCKS (ZB + XB + EB + NB)

// Scratch: fully rewritten each call or self-resetting (cursors via tickets).
__device__ __align__(16) float4 g_x4[NN];   // padded node coords
__device__ int2     g_epair[BB * ESEG];     // edge endpoints grouped by batch
__device__ unsigned g_ecur[BB];             // relative cursors (0 at call start)
__device__ unsigned g_edone[BB];            // NCH_E-reader tickets (wrap reset)
__device__ int      g_noff[BB + 1];

// ---------------- K1: zero out | x4 pad | edge scatter | boundaries ----------------
__global__ void __launch_bounds__(256)
prep_kernel(const float* __restrict__ x,
            const int* __restrict__ ei,
            const int* __restrict__ batch,
            float* __restrict__ out) {
    const int blk = blockIdx.x, tid = threadIdx.x;
    if (blk < ZB) {
        ((float4*)out)[blk * 256 + tid] = make_float4(0.f, 0.f, 0.f, 0.f);
    } else if (blk < ZB + XB) {
        int n = (blk - ZB) * 256 + tid;
        if (n < NN) {
            const float* xp = x + n * 3;
            g_x4[n] = make_float4(__ldg(xp), __ldg(xp + 1), __ldg(xp + 2), 0.f);
        }
    } else if (blk < ZB + XB + EB) {
        __shared__ unsigned scnt[BB], sbase[BB];
        int e = (blk - ZB - XB) * 256 + tid;
        if (tid < BB) scnt[tid] = 0u;
        __syncthreads();
        bool valid = e < EE;
        int s = 0, d = 0, b = 0; unsigned r = 0;
        if (valid) {
            s = __ldg(ei + e); d = __ldg(ei + EE + e);
            b = __ldg(batch + s);
            r = atomicAdd(&scnt[b], 1u);           // block-local rank
        }
        __syncthreads();
        if (tid < BB && scnt[tid])
            sbase[tid] = atomicAdd(&g_ecur[tid], scnt[tid]);
        __syncthreads();
        if (valid) {
            unsigned pos = sbase[b] + r;
            if (pos < ESEG) g_epair[b * ESEG + pos] = make_int2(s, d);
        }
    } else {
        int n = (blk - ZB - XB - EB) * 256 + tid;
        if (n < NN) {
            int bn = batch[n];
            int bp = (n == 0) ? -1 : batch[n - 1];
            for (int b2 = bp + 1; b2 <= bn; ++b2) g_noff[b2] = n;
            if (n == NN - 1)
                for (int b2 = bn + 1; b2 <= BB; ++b2) g_noff[b2] = NN;
        }
    }
}

// Clamp-free nearest-point delta update. u clamped to [-1,32] BEFORE rounding:
// guard bins absorb out-of-range mass (bin -1 = prefix seed, bins 32/33 unread).
// |frac| <= 0.5 -> |arg| <= 9.31: raw ex2.approx is exact-enough and safe.
__device__ __forceinline__ void bin_update(float h, float w, float* __restrict__ my) {
    float u  = fmaf(h, INV_STEP, INV_STEP);
    float uc = fminf(fmaxf(u, -1.0f), 32.0f);
    int   p  = __float2int_rn(uc);
    float fr = uc - (float)p;
    float arg = fr * C_STEP;
    float epow;
    asm("ex2.approx.f32 %0, %1;" : "=f"(epow) : "f"(arg));
    float sig = __fdividef(1.0f, 1.0f + epow);
    float ws = w * sig;
    float* q = my + (p + 1);
    q[0] += ws;            // exact sigmoid at lin point p
    q[1] += w - ws;        // step remainder (s > p)
}

// ---------------- K2: 256-thread blocks, 4 subchunks, float4 coords ----------------
__global__ void __launch_bounds__(256)
hist_kernel(const float* __restrict__ v,
            float* __restrict__ out) {
    __shared__ float hist[HISTF];
    __shared__ int s_tot;

    const int tid = threadIdx.x;
    const int lane = tid & 31, wid = tid >> 5;
    const int c = tid >> 6;              // subchunk 0..3
    const int t = tid & 63;              // theta
    float* my = hist + tid * ROWW;

    const int vb = blockIdx.x;
    const bool is_node = vb < NODE_VB;
    int b, chunk, tot = 0, nch, off = 0;
    float w;
    if (is_node) {
        b = vb >> 3; chunk = vb & 7;
        off = g_noff[b];
        tot = g_noff[b + 1] - off; nch = NCH_N; w = 1.0f;
    } else {
        int eb = vb - NODE_VB;
        b = eb >> 4; chunk = eb & 15;
        nch = NCH_E; w = -0.5f;
        if (tid == 0) {
            unsigned cnt = atomicAdd(&g_ecur[b], 0u);
            s_tot = (cnt > (unsigned)ESEG) ? ESEG : (int)cnt;
            __threadfence();
            unsigned old = atomicInc(&g_edone[b], NCH_E - 1u);
            if (old == NCH_E - 1u) g_ecur[b] = 0u;        // last reader resets
        }
    }
    for (int i2 = tid; i2 < HISTF / 4; i2 += 256)        // vectorized zero
        ((float4*)hist)[i2] = make_float4(0.f, 0.f, 0.f, 0.f);
    __syncthreads();
    if (!is_node) tot = s_tot;

    int per = (tot + nch - 1) / nch;
    int cs = chunk * per;
    int ce = min(tot, cs + per);
    int sub = (per + 3) >> 2;
    int ms = cs + c * sub;
    int me = min(ce, ms + sub);

    float v0 = __ldg(v + t), v1 = __ldg(v + TT + t), v2 = __ldg(v + 2 * TT + t);

    if (is_node) {
        #pragma unroll 4
        for (int i = ms; i < me; i++) {
            float4 xp = __ldg(&g_x4[off + i]);            // 1 broadcast LDG.128
            float h = fmaf(xp.x, v0, fmaf(xp.y, v1, xp.z * v2));
            bin_update(h, w, my);
        }
    } else {
        const int2* ep = g_epair + b * ESEG;
        #pragma unroll 4
        for (int i = ms; i < me; i++) {
            int2 pr = __ldg(ep + i);                      // uniform broadcast
            float4 xs = __ldg(&g_x4[pr.x]);               // 2 broadcast LDG.128
            float4 xd = __ldg(&g_x4[pr.y]);
            float hs = fmaf(xs.x, v0, fmaf(xs.y, v1, xs.z * v2));
            float hd = fmaf(xd.x, v0, fmaf(xd.y, v1, xd.z * v2));
            bin_update(fmaxf(hs, hd), w, my);
        }
    }
    __syncthreads();

    // Fused 4-way merge + prefix over s + flush (2 warps, lanes = t; stride-35 CF).
    if (wid < 2) {
        int tt = wid * 32 + lane;
        const float* h0 = hist + tt * ROWW;
        const float* h1 = hist + (64 + tt) * ROWW;
        const float* h2 = hist + (128 + tt) * ROWW;
        const float* h3 = hist + (192 + tt) * ROWW;
        float run = h0[0] + h1[0] + h2[0] + h3[0];        // guard bin -1 seeds prefix
        #pragma unroll
        for (int s = 0; s < SS; s++) {
            run += h0[s + 1] + h1[s + 1] + h2[s + 1] + h3[s + 1];
            atomicAdd(&out[(b * SS + s) * TT + tt], run);
        }
    }
}

extern "C" void kernel_launch(void* const* d_in, const int* in_sizes, int n_in,
                              void* d_out, int out_size) {
    const float* x     = (const float*)d_in[0];
    const float* v     = (const float*)d_in[1];
    const int*   ei    = (const int*)d_in[3];
    const int*   batch = (const int*)d_in[4];
    float* out = (float*)d_out;

    prep_kernel<<<PREP_BLOCKS, 256>>>(x, ei, batch, out);
    hist_kernel<<<HIST_VB, 256>>>(v, out);
}

// round 17
// speedup vs baseline: 1.6601x; 1.6601x over previous
#include <cuda_runtime.h>

#define NN 20000
#define EE 40000
#define BB 32
#define SS 32
#define TT 64

#define INV_STEP 15.5f          // (S-1)/(2*R)
#define C_BASE   288.5390082f   // 200*log2(e)
#define C_STEP   18.61541988f   // C_BASE/15.5

#define ESEG  2048
#define NCH_N 8
#define NCH_E 16
#define NODE_VB (BB * NCH_N)          // 256
#define EDGE_VB (BB * NCH_E)          // 512
#define HIST_VB (NODE_VB + EDGE_VB)   // 768

// prep block ranges
#define ZB 64                          // zero out: 64*256 float4
#define XB ((NN + 255) / 256)          // 79  : pad x -> float4
#define EB ((EE + 255) / 256)          // 157 : edge scatter
#define NB ((NN + 255) / 256)          // 79  : boundaries
#define PREP_BLOCKS (ZB + XB + EB + NB)

// Scratch: fully rewritten each call or self-resetting (cursors via tickets).
__device__ __align__(16) float4 g_x4[NN];   // padded node coords
__device__ int2     g_epair[BB * ESEG];     // edge endpoints grouped by batch
__device__ unsigned g_ecur[BB];             // relative cursors (0 at call start)
__device__ unsigned g_edone[BB];            // NCH_E-reader tickets (wrap reset)
__device__ int      g_noff[BB + 1];

// ---------------- K1: zero out | x4 pad | edge scatter | boundaries ----------------
__global__ void __launch_bounds__(256)
prep_kernel(const float* __restrict__ x,
            const int* __restrict__ ei,
            const int* __restrict__ batch,
            float* __restrict__ out) {
    const int blk = blockIdx.x, tid = threadIdx.x;
    if (blk < ZB) {
        ((float4*)out)[blk * 256 + tid] = make_float4(0.f, 0.f, 0.f, 0.f);
    } else if (blk < ZB + XB) {
        int n = (blk - ZB) * 256 + tid;
        if (n < NN) {
            const float* xp = x + n * 3;
            g_x4[n] = make_float4(__ldg(xp), __ldg(xp + 1), __ldg(xp + 2), 0.f);
        }
    } else if (blk < ZB + XB + EB) {
        __shared__ unsigned scnt[BB], sbase[BB];
        int e = (blk - ZB - XB) * 256 + tid;
        if (tid < BB) scnt[tid] = 0u;
        __syncthreads();
        bool valid = e < EE;
        int s = 0, d = 0, b = 0; unsigned r = 0;
        if (valid) {
            s = __ldg(ei + e); d = __ldg(ei + EE + e);
            b = __ldg(batch + s);
            r = atomicAdd(&scnt[b], 1u);           // block-local rank
        }
        __syncthreads();
        if (tid < BB && scnt[tid])
            sbase[tid] = atomicAdd(&g_ecur[tid], scnt[tid]);   // one per (block,batch)
        __syncthreads();
        if (valid) {
            unsigned pos = sbase[b] + r;
            if (pos < ESEG) g_epair[b * ESEG + pos] = make_int2(s, d);
        }
    } else {
        int n = (blk - ZB - XB - EB) * 256 + tid;
        if (n < NN) {
            int bn = batch[n];
            int bp = (n == 0) ? -1 : batch[n - 1];
            for (int b2 = bp + 1; b2 <= bn; ++b2) g_noff[b2] = n;
            if (n == NN - 1)
                for (int b2 = bn + 1; b2 <= BB; ++b2) g_noff[b2] = NN;
        }
    }
}

// Nearest-point delta update (R14-proven): p = round((h+1)*15.5) is the one
// exact-sigmoid point.  d[p] += w*sig;  d[p+1] += w - w*sig.  Predicated adds
// let ptxas skip the smem RMW entirely when p is out of range (~1/3 of pairs).
__device__ __forceinline__ void bin_update(float h, float w, float* __restrict__ my) {
    float u = fmaf(h, INV_STEP, INV_STEP);
    int p = __float2int_rn(u);
    float epow = exp2f(fmaf((float)p, -C_STEP, fmaf(h, C_BASE, C_BASE)));  // exp(-z) at p
    float sig = __fdividef(1.0f, 1.0f + epow);
    float ws = w * sig;
    int c1 = min(max(p, 0), SS - 1);
    my[c1] += ((p >= 0) & (p < SS)) ? ws : 0.0f;
    int q = p + 1;
    float hv = (p >= 0) ? (w - ws) : w;      // p<0: all cells get full w
    int c2 = min(max(q, 0), SS - 1);
    my[c2] += (q < SS) ? hv : 0.0f;
}

// ---------------- K2: 256-thread blocks, 4 subchunks, float4 coords ----------------
__global__ void __launch_bounds__(256)
hist_kernel(const float* __restrict__ v,
            float* __restrict__ out) {
    __shared__ float hist[256 * 33];     // thread-private 33-float delta rows
    __shared__ int s_tot;

    const int tid = threadIdx.x;
    const int lane = tid & 31, wid = tid >> 5;
    const int c = tid >> 6;              // subchunk 0..3
    const int t = tid & 63;              // theta
    float* my = hist + tid * 33;

    const int vb = blockIdx.x;
    const bool is_node = vb < NODE_VB;
    int b, chunk, tot = 0, nch, off = 0;
    float w;
    if (is_node) {
        b = vb >> 3; chunk = vb & 7;
        off = g_noff[b];
        tot = g_noff[b + 1] - off; nch = NCH_N; w = 1.0f;
    } else {
        int eb = vb - NODE_VB;
        b = eb >> 4; chunk = eb & 15;
        nch = NCH_E; w = -0.5f;
        if (tid == 0) {
            unsigned cnt = atomicAdd(&g_ecur[b], 0u);
            s_tot = (cnt > (unsigned)ESEG) ? ESEG : (int)cnt;
            __threadfence();
            unsigned old = atomicInc(&g_edone[b], NCH_E - 1u);
            if (old == NCH_E - 1u) g_ecur[b] = 0u;        // last reader resets
        }
    }
    for (int i2 = tid; i2 < 256 * 33; i2 += 256) hist[i2] = 0.0f;
    __syncthreads();
    if (!is_node) tot = s_tot;

    int per = (tot + nch - 1) / nch;
    int cs = chunk * per;
    int ce = min(tot, cs + per);
    int sub = (per + 3) >> 2;
    int ms = cs + c * sub;
    int me = min(ce, ms + sub);

    float v0 = __ldg(v + t), v1 = __ldg(v + TT + t), v2 = __ldg(v + 2 * TT + t);

    if (is_node) {
        #pragma unroll 4
        for (int i = ms; i < me; i++) {
            float4 xp = __ldg(&g_x4[off + i]);            // 1 broadcast LDG.128
            float h = fmaf(xp.x, v0, fmaf(xp.y, v1, xp.z * v2));
            bin_update(h, w, my);
        }
    } else {
        const int2* ep = g_epair + b * ESEG;
        #pragma unroll 4
        for (int i = ms; i < me; i++) {
            int2 pr = __ldg(ep + i);                      // uniform broadcast
            float4 xs = __ldg(&g_x4[pr.x]);               // 2 broadcast LDG.128
            float4 xd = __ldg(&g_x4[pr.y]);
            float hs = fmaf(xs.x, v0, fmaf(xs.y, v1, xs.z * v2));
            float hd = fmaf(xd.x, v0, fmaf(xd.y, v1, xd.z * v2));
            bin_update(fmaxf(hs, hd), w, my);
        }
    }
    __syncthreads();

    // Fused 4-way merge + prefix-scan over s + flush (2 warps, lanes = t).
    if (wid < 2) {
        int tt = wid * 32 + lane;
        const float* h0 = hist + tt * 33;
        const float* h1 = hist + (64 + tt) * 33;
        const float* h2 = hist + (128 + tt) * 33;
        const float* h3 = hist + (192 + tt) * 33;
        float run = 0.0f;
        #pragma unroll
        for (int s = 0; s < SS; s++) {
            run += h0[s] + h1[s] + h2[s] + h3[s];
            atomicAdd(&out[(b * SS + s) * TT + tt], run);
        }
    }
}

extern "C" void kernel_launch(void* const* d_in, const int* in_sizes, int n_in,
                              void* d_out, int out_size) {
    const float* x     = (const float*)d_in[0];
    const float* v     = (const float*)d_in[1];
    const int*   ei    = (const int*)d_in[3];
    const int*   batch = (const int*)d_in[4];
    float* out = (float*)d_out;

    prep_kernel<<<PREP_BLOCKS, 256>>>(x, ei, batch, out);
    hist_kernel<<<HIST_VB, 256>>>(v, out);
}